// round 16
// baseline (speedup 1.0000x reference)
#include <cuda_runtime.h>

// OpenLSTM: B=4096 sequences, T=1024, HID=16, PROJ=2.
// t < 256 teacher-forced; t >= 256 recurrent.
//
// R16 = R15 (184.8us) + fma.rn.f32x2 (FFMA2) packing of the gate and xp FMAs:
// recurrent 8 gate FMA -> 4 FFMA2 + 2 dup, xp 8 -> 4+2; teacher gates 16 -> 12
// per step. IEEE-exact (fma.rn), chain unchanged; targets the issue-count half
// of the recurrent budget (3.46 warps x 49 instr ~ 170/SMSP ~ chain 172).
// Butterfly/TANH/c-path/stores byte-identical to R15.
// Layout: TPE=16, 2 elem/warp, 2048 warps. Folded sigmoids, hc-trick, RU=4.

#define T_TOTAL 1024
#define N_CTX   256
#define TPE     16
#define EPB     4     // elements per 64-thread block
#define TU      4     // teacher-phase time unroll
#define RU      4     // recurrent block unroll

typedef unsigned long long u64;

__device__ __forceinline__ float tanh_fast(float x) {
    float y;
    asm("tanh.approx.f32 %0, %1;" : "=f"(y) : "f"(x));
    return y;
}

// ---- f32x2 packed helpers (sm_103a FFMA2 path) ----
__device__ __forceinline__ u64 pack2(float a, float b) {
    u64 r;
    asm("mov.b64 %0, {%1, %2};"
        : "=l"(r) : "r"(__float_as_uint(a)), "r"(__float_as_uint(b)));
    return r;
}
__device__ __forceinline__ u64 dup2(float a) {
    u64 r;
    asm("mov.b64 %0, {%1, %1};" : "=l"(r) : "r"(__float_as_uint(a)));
    return r;
}
__device__ __forceinline__ float2 unpack2(u64 v) {
    unsigned lo, hi;
    asm("mov.b64 {%0, %1}, %2;" : "=r"(lo), "=r"(hi) : "l"(v));
    return make_float2(__uint_as_float(lo), __uint_as_float(hi));
}
__device__ __forceinline__ u64 fma2(u64 a, u64 b, u64 c) {
    u64 r;
    asm("fma.rn.f32x2 %0, %1, %2, %3;" : "=l"(r) : "l"(a), "l"(b), "l"(c));
    return r;
}

// Predicated stores (no BSSY/BSYNC)
__device__ __forceinline__ void store2_if(int j, float2* addr, float a, float b) {
    asm volatile(
        "{ .reg .pred p; setp.eq.s32 p, %0, 0; @p st.global.v2.f32 [%1], {%2, %3}; }"
        :: "r"(j), "l"(addr), "f"(a), "f"(b) : "memory");
}
__device__ __forceinline__ void store1_if(int pred32, float* addr, float a) {
    asm volatile(
        "{ .reg .pred p; setp.eq.s32 p, %0, 0; @p st.global.f32 [%1], %2; }"
        :: "r"(pred32), "l"(addr), "f"(a) : "memory");
}

__global__ void __launch_bounds__(64)
open_lstm_kernel(const float* __restrict__ u,     // (B, T, 4)
                 const float* __restrict__ w_ih,  // (64, 2)
                 const float* __restrict__ w_hh,  // (64, 2)
                 const float* __restrict__ b_ih,  // (64)
                 const float* __restrict__ b_hh,  // (64)
                 const float* __restrict__ w_hr,  // (2, 16)
                 float* __restrict__ out)         // (B, T, 2)
{
    const int tid  = threadIdx.x;
    const int j    = tid & (TPE - 1);                 // hidden unit 0..15
    const int e    = blockIdx.x * EPB + (tid >> 4);   // element index
    const bool lo8 = (j < 8);
    const int  jm8 = j & 7;                           // 0 only for lanes 0 and 8
    const int  so  = (j >> 3) & 1;                    // 0 -> h.x slot, 1 -> h.y

    // Weights for unit j. sigma(x)=0.5*tanh(0.5x)+0.5 folded: i/f/o gate rows
    // pre-scaled by 0.5; o-path outer 0.5 folded into w_hr.
    float wi[4][2], wh[4][2], bb[4], wr0, wr1;
#pragma unroll
    for (int k = 0; k < 4; k++) {
        const int r = k * 16 + j;
        const float sc = (k == 2) ? 1.0f : 0.5f;
        wi[k][0] = w_ih[r * 2 + 0] * sc;
        wi[k][1] = w_ih[r * 2 + 1] * sc;
        wh[k][0] = w_hh[r * 2 + 0] * sc;
        wh[k][1] = w_hh[r * 2 + 1] * sc;
        bb[k]    = (b_ih[r] + b_hh[r]) * sc;
    }
    wr0 = w_hr[j]      * 0.5f;
    wr1 = w_hr[16 + j] * 0.5f;

    // Packed weight pairs: A = gates (i,f), B = gates (g,o)
    const u64 wiA0 = pack2(wi[0][0], wi[1][0]), wiA1 = pack2(wi[0][1], wi[1][1]);
    const u64 wiB0 = pack2(wi[2][0], wi[3][0]), wiB1 = pack2(wi[2][1], wi[3][1]);
    const u64 whA0 = pack2(wh[0][0], wh[1][0]), whA1 = pack2(wh[0][1], wh[1][1]);
    const u64 whB0 = pack2(wh[2][0], wh[3][0]), whB1 = pack2(wh[2][1], wh[3][1]);
    const u64 bbA  = pack2(bb[0], bb[1]),       bbB  = pack2(bb[2], bb[3]);

    const float4* __restrict__ up = (const float4*)u + (size_t)e * T_TOTAL;
    float2* __restrict__ op       = (float2*)out + (size_t)e * T_TOTAL;
    float* __restrict__ opf       = (float*)op;

    float hc = 0.0f;               // c/2 (state)
    float h0 = 0.0f, h1 = 0.0f;

    // ======== teacher-forced phase: packed gates, segregated 4-SHFL reduce ===
    float rlast = 0.0f;
#pragma unroll 1
    for (int t = 0; t < N_CTX; t += TU) {
        float4 vv[TU];
#pragma unroll
        for (int s = 0; s < TU; s++) vv[s] = up[t + s];

        float ti[TU], tf[TU], tg[TU], to[TU];
#pragma unroll
        for (int s = 0; s < TU; s++) {
            u64 xd = dup2(vv[s].x), yd = dup2(vv[s].y);
            u64 zd = dup2(vv[s].z), wd = dup2(vv[s].w);
            u64 gA = fma2(wiA0, xd, fma2(wiA1, yd,
                     fma2(whA0, zd, fma2(whA1, wd, bbA))));
            u64 gB = fma2(wiB0, xd, fma2(wiB1, yd,
                     fma2(whB0, zd, fma2(whB1, wd, bbB))));
            float2 ga = unpack2(gA), gb = unpack2(gB);
            ti[s] = tanh_fast(ga.x);
            tf[s] = tanh_fast(ga.y);
            tg[s] = tanh_fast(gb.x);
            to[s] = tanh_fast(gb.y);
        }

        float tc[TU];
#pragma unroll
        for (int s = 0; s < TU; s++) {
            float ca = fmaf(tf[s], hc, hc);          // sigma(f)*c
            float cb = fmaf(ti[s], tg[s], tg[s]);    // 2*sigma(i)*tanh(g)
            float cf = fmaf(0.5f, cb, ca);           // new c
            tc[s] = tanh_fast(cf);
            hc = 0.5f * cf;                          // off-chain state update
        }

        float rr[TU];
#pragma unroll
        for (int s = 0; s < TU; s++) {
            float b0 = fmaf(wr0, to[s], wr0);        // wr0*(1+to)
            float b1 = fmaf(wr1, to[s], wr1);
            float p0 = b0 * tc[s];
            float p1 = b1 * tc[s];
            float send = lo8 ? p1 : p0;
            float keep = lo8 ? p0 : p1;
            float r = keep + __shfl_xor_sync(0xffffffffu, send, 8);
            r += __shfl_xor_sync(0xffffffffu, r, 1);
            r += __shfl_xor_sync(0xffffffffu, r, 2);
            r += __shfl_xor_sync(0xffffffffu, r, 4);
            rr[s] = r;
        }
#pragma unroll
        for (int s = 0; s < TU; s++)
            store1_if(jm8, opf + 2 * (t + s) + so, rr[s]);
        rlast = rr[TU - 1];
    }

    // phase boundary: single broadcast of final teacher h into all lanes
    {
        float o2 = __shfl_xor_sync(0xffffffffu, rlast, 8);
        h0 = lo8 ? rlast : o2;
        h1 = lo8 ? o2 : rlast;
    }

    // ================= recurrent phase: packed gates/xp, RU=4 ================
    u64 xpA, xpB;
    {
        float4 v0 = up[N_CTX];
        u64 xd = dup2(v0.x), yd = dup2(v0.y);
        xpA = fma2(wiA0, xd, fma2(wiA1, yd, bbA));
        xpB = fma2(wiB0, xd, fma2(wiB1, yd, bbB));
    }

#pragma unroll 1
    for (int t = N_CTX; t < T_TOTAL - RU; t += RU) {
        float4 vn[RU];
#pragma unroll
        for (int s = 0; s < RU; s++) vn[s] = up[t + 1 + s];

        u64 xpnA[RU], xpnB[RU];
#pragma unroll
        for (int s = 0; s < RU; s++) {
            u64 xd = dup2(vn[s].x), yd = dup2(vn[s].y);
            xpnA[s] = fma2(wiA0, xd, fma2(wiA1, yd, bbA));
            xpnB[s] = fma2(wiB0, xd, fma2(wiB1, yd, bbB));
        }

#pragma unroll
        for (int s = 0; s < RU; s++) {
            const u64 xA = (s == 0) ? xpA : xpnA[s - 1];
            const u64 xB = (s == 0) ? xpB : xpnB[s - 1];

            u64 H0d = dup2(h0), H1d = dup2(h1);
            u64 gA = fma2(whA0, H0d, fma2(whA1, H1d, xA));   // (gi, gf)
            u64 gB = fma2(whB0, H0d, fma2(whB1, H1d, xB));   // (gg, go)
            float2 ga = unpack2(gA), gb = unpack2(gB);

            float ti = tanh_fast(ga.x);
            float tf = tanh_fast(ga.y);
            float tg = tanh_fast(gb.x);
            float to = tanh_fast(gb.y);

            float ca = fmaf(tf, hc, hc);             // sigma(f)*c
            float cb = fmaf(ti, tg, tg);             // 2*sigma(i)*tanh(g)
            float cf = fmaf(0.5f, cb, ca);           // new c
            float tc = tanh_fast(cf);
            hc = 0.5f * cf;                          // off-chain

            float b0 = fmaf(wr0, to, wr0);           // off-chain during tanh
            float b1 = fmaf(wr1, to, wr1);

            float p0 = b0 * tc;
            float p1 = b1 * tc;
#pragma unroll
            for (int k = 1; k < TPE; k <<= 1) {
                p0 += __shfl_xor_sync(0xffffffffu, p0, k, TPE);
                p1 += __shfl_xor_sync(0xffffffffu, p1, k, TPE);
            }
            h0 = p0; h1 = p1;
            store2_if(j, op + (t + s), p0, p1);
        }
        xpA = xpnA[RU - 1];
        xpB = xpnB[RU - 1];
    }

    // -------- epilogue: last RU steps, clamped prefetch --------
#pragma unroll 1
    for (int t = T_TOTAL - RU; t < T_TOTAL; t++) {
        float4 vn = up[(t + 1 < T_TOTAL) ? (t + 1) : t];

        u64 H0d = dup2(h0), H1d = dup2(h1);
        u64 gA = fma2(whA0, H0d, fma2(whA1, H1d, xpA));
        u64 gB = fma2(whB0, H0d, fma2(whB1, H1d, xpB));
        float2 ga = unpack2(gA), gb = unpack2(gB);

        float ti = tanh_fast(ga.x);
        float tf = tanh_fast(ga.y);
        float tg = tanh_fast(gb.x);
        float to = tanh_fast(gb.y);

        float ca = fmaf(tf, hc, hc);
        float cb = fmaf(ti, tg, tg);
        float cf = fmaf(0.5f, cb, ca);
        float tc = tanh_fast(cf);
        hc = 0.5f * cf;

        float b0 = fmaf(wr0, to, wr0);
        float b1 = fmaf(wr1, to, wr1);

        float p0 = b0 * tc;
        float p1 = b1 * tc;
#pragma unroll
        for (int k = 1; k < TPE; k <<= 1) {
            p0 += __shfl_xor_sync(0xffffffffu, p0, k, TPE);
            p1 += __shfl_xor_sync(0xffffffffu, p1, k, TPE);
        }
        h0 = p0; h1 = p1;
        store2_if(j, op + t, p0, p1);

        u64 xd = dup2(vn.x), yd = dup2(vn.y);
        xpA = fma2(wiA0, xd, fma2(wiA1, yd, bbA));
        xpB = fma2(wiB0, xd, fma2(wiB1, yd, bbB));
    }
}

extern "C" void kernel_launch(void* const* d_in, const int* in_sizes, int n_in,
                              void* d_out, int out_size)
{
    const float* u    = (const float*)d_in[0];
    const float* w_ih = (const float*)d_in[1];
    const float* w_hh = (const float*)d_in[2];
    const float* b_ih = (const float*)d_in[3];
    const float* b_hh = (const float*)d_in[4];
    const float* w_hr = (const float*)d_in[5];
    float* out = (float*)d_out;

    const int B = in_sizes[0] / (T_TOTAL * 4);   // 4096
    const int grid = B / EPB;                    // 1024 blocks x 64 threads

    open_lstm_kernel<<<grid, 64>>>(u, w_ih, w_hh, b_ih, b_hh, w_hr, out);
}

// round 17
// speedup vs baseline: 1.1028x; 1.1028x over previous
#include <cuda_runtime.h>

// OpenLSTM: B=4096 sequences, T=1024, HID=16, PROJ=2.
// t < 256 teacher-forced; t >= 256 recurrent.
//
// R17 = R15 (184.8us best; FFMA2 of R16 reverted) with deeper batching only:
//  - TU=8 teacher (was 4): more independent chains in flight per iter,
//    half the loop overhead; teacher measured 210 cyc/step vs ~150 floor.
//  - RU=8 recurrent blocks (was 4): half the block-loop overhead, bigger
//    independent LDG/xp filler chunk.
// Step code (gates, folded sigmoids, hc-trick, R5 butterfly, predicated
// stores) byte-identical to R15. TPE=16, 2 elem/warp, 2048 warps.

#define T_TOTAL 1024
#define N_CTX   256
#define TPE     16
#define EPB     4     // elements per 64-thread block
#define TU      8     // teacher-phase time unroll
#define RU      8     // recurrent block unroll

__device__ __forceinline__ float tanh_fast(float x) {
    float y;
    asm("tanh.approx.f32 %0, %1;" : "=f"(y) : "f"(x));
    return y;
}

// Predicated 8-byte store (no BSSY/BSYNC): if (j==0) st.v2 [addr]
__device__ __forceinline__ void store2_if(int j, float2* addr, float a, float b) {
    asm volatile(
        "{ .reg .pred p; setp.eq.s32 p, %0, 0; @p st.global.v2.f32 [%1], {%2, %3}; }"
        :: "r"(j), "l"(addr), "f"(a), "f"(b) : "memory");
}

// Predicated 4-byte store: if (pred32 == 0) st.f32 [addr]
__device__ __forceinline__ void store1_if(int pred32, float* addr, float a) {
    asm volatile(
        "{ .reg .pred p; setp.eq.s32 p, %0, 0; @p st.global.f32 [%1], %2; }"
        :: "r"(pred32), "l"(addr), "f"(a) : "memory");
}

__global__ void __launch_bounds__(64)
open_lstm_kernel(const float* __restrict__ u,     // (B, T, 4)
                 const float* __restrict__ w_ih,  // (64, 2)
                 const float* __restrict__ w_hh,  // (64, 2)
                 const float* __restrict__ b_ih,  // (64)
                 const float* __restrict__ b_hh,  // (64)
                 const float* __restrict__ w_hr,  // (2, 16)
                 float* __restrict__ out)         // (B, T, 2)
{
    const int tid  = threadIdx.x;
    const int j    = tid & (TPE - 1);                 // hidden unit 0..15
    const int e    = blockIdx.x * EPB + (tid >> 4);   // element index
    const bool lo8 = (j < 8);
    const int  jm8 = j & 7;                           // 0 only for lanes 0 and 8
    const int  so  = (j >> 3) & 1;                    // 0 -> h.x slot, 1 -> h.y

    // Weights for unit j. sigma(x)=0.5*tanh(0.5x)+0.5 folded: i/f/o gate rows
    // pre-scaled by 0.5; o-path outer 0.5 folded into w_hr.
    float wi[4][2], wh[4][2], bb[4], wr0, wr1;
#pragma unroll
    for (int k = 0; k < 4; k++) {
        const int r = k * 16 + j;
        const float sc = (k == 2) ? 1.0f : 0.5f;
        wi[k][0] = w_ih[r * 2 + 0] * sc;
        wi[k][1] = w_ih[r * 2 + 1] * sc;
        wh[k][0] = w_hh[r * 2 + 0] * sc;
        wh[k][1] = w_hh[r * 2 + 1] * sc;
        bb[k]    = (b_ih[r] + b_hh[r]) * sc;
    }
    wr0 = w_hr[j]      * 0.5f;
    wr1 = w_hr[16 + j] * 0.5f;

    const float4* __restrict__ up = (const float4*)u + (size_t)e * T_TOTAL;
    float2* __restrict__ op       = (float2*)out + (size_t)e * T_TOTAL;
    float* __restrict__ opf       = (float*)op;

    float hc = 0.0f;               // c/2 (state)
    float h0 = 0.0f, h1 = 0.0f;

    // ======== teacher-forced phase: segregated 4-SHFL reduce, unrolled x8 ====
    float rlast = 0.0f;            // segregated h (h0 on lanes<8, h1 on lanes>=8)
#pragma unroll 1
    for (int t = 0; t < N_CTX; t += TU) {
        float4 vv[TU];
#pragma unroll
        for (int s = 0; s < TU; s++) vv[s] = up[t + s];

        float ti[TU], tf[TU], tg[TU], to[TU];
#pragma unroll
        for (int s = 0; s < TU; s++) {
            float gi = fmaf(wi[0][0], vv[s].x, fmaf(wi[0][1], vv[s].y,
                       fmaf(wh[0][0], vv[s].z, fmaf(wh[0][1], vv[s].w, bb[0]))));
            float gf = fmaf(wi[1][0], vv[s].x, fmaf(wi[1][1], vv[s].y,
                       fmaf(wh[1][0], vv[s].z, fmaf(wh[1][1], vv[s].w, bb[1]))));
            float gg = fmaf(wi[2][0], vv[s].x, fmaf(wi[2][1], vv[s].y,
                       fmaf(wh[2][0], vv[s].z, fmaf(wh[2][1], vv[s].w, bb[2]))));
            float go = fmaf(wi[3][0], vv[s].x, fmaf(wi[3][1], vv[s].y,
                       fmaf(wh[3][0], vv[s].z, fmaf(wh[3][1], vv[s].w, bb[3]))));
            ti[s] = tanh_fast(gi);
            tf[s] = tanh_fast(gf);
            tg[s] = tanh_fast(gg);
            to[s] = tanh_fast(go);
        }

        float tc[TU];
#pragma unroll
        for (int s = 0; s < TU; s++) {
            float ca = fmaf(tf[s], hc, hc);          // sigma(f)*c
            float cb = fmaf(ti[s], tg[s], tg[s]);    // 2*sigma(i)*tanh(g)
            float cf = fmaf(0.5f, cb, ca);           // new c
            tc[s] = tanh_fast(cf);
            hc = 0.5f * cf;                          // off-chain state update
        }

        float rr[TU];
#pragma unroll
        for (int s = 0; s < TU; s++) {
            float b0 = fmaf(wr0, to[s], wr0);        // wr0*(1+to)
            float b1 = fmaf(wr1, to[s], wr1);
            float p0 = b0 * tc[s];
            float p1 = b1 * tc[s];
            // segregate: lanes<8 accumulate p0, lanes>=8 accumulate p1
            float send = lo8 ? p1 : p0;
            float keep = lo8 ? p0 : p1;
            float r = keep + __shfl_xor_sync(0xffffffffu, send, 8);
            r += __shfl_xor_sync(0xffffffffu, r, 1);
            r += __shfl_xor_sync(0xffffffffu, r, 2);
            r += __shfl_xor_sync(0xffffffffu, r, 4);
            rr[s] = r;
        }
        // 2-lane predicated scalar stores: lane0 -> h.x, lane8 -> h.y
#pragma unroll
        for (int s = 0; s < TU; s++)
            store1_if(jm8, opf + 2 * (t + s) + so, rr[s]);
        rlast = rr[TU - 1];
    }

    // phase boundary: single broadcast of final teacher h into all lanes
    {
        float o2 = __shfl_xor_sync(0xffffffffu, rlast, 8);
        h0 = lo8 ? rlast : o2;
        h1 = lo8 ? o2 : rlast;
    }

    // ================= recurrent phase: RU=8 blocks ==========================
    float xp[4];
    {
        float4 v0 = up[N_CTX];
#pragma unroll
        for (int k = 0; k < 4; k++)
            xp[k] = fmaf(wi[k][0], v0.x, fmaf(wi[k][1], v0.y, bb[k]));
    }

#pragma unroll 1
    for (int t = N_CTX; t < T_TOTAL - RU; t += RU) {
        // batched loads for steps t+1 .. t+RU (always in range here)
        float4 vn[RU];
#pragma unroll
        for (int s = 0; s < RU; s++) vn[s] = up[t + 1 + s];

        // batched xp for the NEXT RU steps (independent of h -> filler work)
        float xpn[RU][4];
#pragma unroll
        for (int s = 0; s < RU; s++)
#pragma unroll
            for (int k = 0; k < 4; k++)
                xpn[s][k] = fmaf(wi[k][0], vn[s].x,
                            fmaf(wi[k][1], vn[s].y, bb[k]));

#pragma unroll
        for (int s = 0; s < RU; s++) {
            const float* xps = (s == 0) ? xp : xpn[s - 1];

            float gi  = fmaf(wh[0][0], h0, fmaf(wh[0][1], h1, xps[0]));
            float gf  = fmaf(wh[1][0], h0, fmaf(wh[1][1], h1, xps[1]));
            float gg2 = fmaf(wh[2][0], h0, fmaf(wh[2][1], h1, xps[2]));
            float go  = fmaf(wh[3][0], h0, fmaf(wh[3][1], h1, xps[3]));

            float ti = tanh_fast(gi);
            float tf = tanh_fast(gf);
            float tg = tanh_fast(gg2);
            float to = tanh_fast(go);

            float ca = fmaf(tf, hc, hc);             // sigma(f)*c
            float cb = fmaf(ti, tg, tg);             // 2*sigma(i)*tanh(g)
            float cf = fmaf(0.5f, cb, ca);           // new c
            float tc = tanh_fast(cf);
            hc = 0.5f * cf;                          // off-chain

            float b0 = fmaf(wr0, to, wr0);           // off-chain during tanh
            float b1 = fmaf(wr1, to, wr1);

            float p0 = b0 * tc;
            float p1 = b1 * tc;
#pragma unroll
            for (int k = 1; k < TPE; k <<= 1) {
                p0 += __shfl_xor_sync(0xffffffffu, p0, k, TPE);
                p1 += __shfl_xor_sync(0xffffffffu, p1, k, TPE);
            }
            h0 = p0; h1 = p1;
            store2_if(j, op + (t + s), p0, p1);
        }
#pragma unroll
        for (int k = 0; k < 4; k++) xp[k] = xpn[RU - 1][k];
    }

    // -------- epilogue: last RU steps, clamped prefetch --------
#pragma unroll 1
    for (int t = T_TOTAL - RU; t < T_TOTAL; t++) {
        float4 vn = up[(t + 1 < T_TOTAL) ? (t + 1) : t];

        float gi  = fmaf(wh[0][0], h0, fmaf(wh[0][1], h1, xp[0]));
        float gf  = fmaf(wh[1][0], h0, fmaf(wh[1][1], h1, xp[1]));
        float gg2 = fmaf(wh[2][0], h0, fmaf(wh[2][1], h1, xp[2]));
        float go  = fmaf(wh[3][0], h0, fmaf(wh[3][1], h1, xp[3]));

        float ti = tanh_fast(gi);
        float tf = tanh_fast(gf);
        float tg = tanh_fast(gg2);
        float to = tanh_fast(go);

        float ca = fmaf(tf, hc, hc);
        float cb = fmaf(ti, tg, tg);
        float cf = fmaf(0.5f, cb, ca);
        float tc = tanh_fast(cf);
        hc = 0.5f * cf;

        float b0 = fmaf(wr0, to, wr0);
        float b1 = fmaf(wr1, to, wr1);

        float p0 = b0 * tc;
        float p1 = b1 * tc;
#pragma unroll
        for (int k = 1; k < TPE; k <<= 1) {
            p0 += __shfl_xor_sync(0xffffffffu, p0, k, TPE);
            p1 += __shfl_xor_sync(0xffffffffu, p1, k, TPE);
        }
        h0 = p0; h1 = p1;
        store2_if(j, op + t, p0, p1);

#pragma unroll
        for (int k = 0; k < 4; k++)
            xp[k] = fmaf(wi[k][0], vn.x, fmaf(wi[k][1], vn.y, bb[k]));
    }
}

extern "C" void kernel_launch(void* const* d_in, const int* in_sizes, int n_in,
                              void* d_out, int out_size)
{
    const float* u    = (const float*)d_in[0];
    const float* w_ih = (const float*)d_in[1];
    const float* w_hh = (const float*)d_in[2];
    const float* b_ih = (const float*)d_in[3];
    const float* b_hh = (const float*)d_in[4];
    const float* w_hr = (const float*)d_in[5];
    float* out = (float*)d_out;

    const int B = in_sizes[0] / (T_TOTAL * 4);   // 4096
    const int grid = B / EPB;                    // 1024 blocks x 64 threads

    open_lstm_kernel<<<grid, 64>>>(u, w_ih, w_hh, b_ih, b_hh, w_hr, out);
}